// round 1
// baseline (speedup 1.0000x reference)
#include <cuda_runtime.h>
#include <cuda_bf16.h>
#include <cstdint>

// Problem constants
constexpr int cB = 8;
constexpr int cN = 1024;
constexpr int cC = 640;
constexpr int cH = 8;
constexpr int cD = 80;
constexpr int cR = 3;
constexpr int cInner = cH * cD;        // 640
constexpr int cM = cB * cN;            // 8192
constexpr int cRN = cR * cN;           // 3072
constexpr float SCALE = 0.11180339887498949f;  // 80^-0.5

// Scratch (static device globals; no allocation allowed)
__device__ float g_q[cM * cInner];
__device__ float g_k[cM * cInner];
__device__ float g_v[cM * cInner];
__device__ float g_ao[cM * cInner];

// ---------------------------------------------------------------------------
// SGEMM: C[M,Nc] = A[M,K] * B[Nc,K]^T (+bias).  Both operands K-contiguous.
// 128x128 block tile, BK=8, 8x8 per-thread, 256 threads.
// M % 128 == 0, Nc % 128 == 0, K % 8 == 0 (holds: 8192, 640, 640).
// ---------------------------------------------------------------------------
__global__ __launch_bounds__(256) void sgemm_nt(
    const float* __restrict__ A, const float* __restrict__ Bm,
    float* __restrict__ C, const float* __restrict__ bias,
    int M, int Nc, int K)
{
    __shared__ float As[8][128];
    __shared__ float Bs[8][128];

    const int tid  = threadIdx.x;
    const int tx   = tid & 15;
    const int ty   = tid >> 4;
    const int lrow = tid >> 1;          // 0..127
    const int lcol = (tid & 1) * 4;     // 0 or 4

    const float* Ap = A  + (size_t)(blockIdx.y * 128 + lrow) * K + lcol;
    const float* Bp = Bm + (size_t)(blockIdx.x * 128 + lrow) * K + lcol;

    float acc[8][8];
#pragma unroll
    for (int i = 0; i < 8; i++)
#pragma unroll
        for (int j = 0; j < 8; j++) acc[i][j] = 0.f;

    for (int k0 = 0; k0 < K; k0 += 8) {
        float4 av = *(const float4*)(Ap + k0);
        float4 bv = *(const float4*)(Bp + k0);
        As[lcol + 0][lrow] = av.x; As[lcol + 1][lrow] = av.y;
        As[lcol + 2][lrow] = av.z; As[lcol + 3][lrow] = av.w;
        Bs[lcol + 0][lrow] = bv.x; Bs[lcol + 1][lrow] = bv.y;
        Bs[lcol + 2][lrow] = bv.z; Bs[lcol + 3][lrow] = bv.w;
        __syncthreads();
#pragma unroll
        for (int kk = 0; kk < 8; kk++) {
            float ra[8], rb[8];
            *(float4*)(ra)     = *(const float4*)&As[kk][ty * 8];
            *(float4*)(ra + 4) = *(const float4*)&As[kk][ty * 8 + 4];
            *(float4*)(rb)     = *(const float4*)&Bs[kk][tx * 8];
            *(float4*)(rb + 4) = *(const float4*)&Bs[kk][tx * 8 + 4];
#pragma unroll
            for (int i = 0; i < 8; i++)
#pragma unroll
                for (int j = 0; j < 8; j++)
                    acc[i][j] = fmaf(ra[i], rb[j], acc[i][j]);
        }
        __syncthreads();
    }

    const int c0 = blockIdx.x * 128 + tx * 8;
    float badd[8];
#pragma unroll
    for (int j = 0; j < 8; j++) badd[j] = bias ? bias[c0 + j] : 0.f;

#pragma unroll
    for (int i = 0; i < 8; i++) {
        const int row = blockIdx.y * 128 + ty * 8 + i;
        float* cp = C + (size_t)row * Nc + c0;
        float4 o0 = make_float4(acc[i][0] + badd[0], acc[i][1] + badd[1],
                                acc[i][2] + badd[2], acc[i][3] + badd[3]);
        float4 o1 = make_float4(acc[i][4] + badd[4], acc[i][5] + badd[5],
                                acc[i][6] + badd[6], acc[i][7] + badd[7]);
        *(float4*)cp       = o0;
        *(float4*)(cp + 4) = o1;
    }
}

// ---------------------------------------------------------------------------
// Flash-style windowed attention.
// Grid: (N/64, H, B). 256 threads = 16x16, 4x4 S-tile per thread.
// Q/K/V tiles stored d-major (transposed) in smem: [80][pitch] so the
// QK^T inner loop is one broadcast LDS.128 (Q) + one conflict-free LDS.128 (K)
// per 16 FFMAs.  P tile round-trips through smem for the PV GEMM.
// Smem: Qs[80][68] + Ks[80][68] + Vs[80][65] + Ps[64][68] = 81728 B (dynamic).
// ---------------------------------------------------------------------------
constexpr int QP = 68;   // pitch for Qs/Ks (mult of 4 for float4)
constexpr int VP = 65;   // pitch for Vs (scalar access, odd => conflict-free)
constexpr int PP = 68;   // pitch for Ps
constexpr int ATTN_SMEM = (80 * QP + 80 * QP + 80 * VP + 64 * PP) * 4;

__global__ __launch_bounds__(256) void attn_kernel(const int* __restrict__ ctx)
{
    const int qt = blockIdx.x;   // query tile 0..15
    const int h  = blockIdx.y;
    const int b  = blockIdx.z;

    extern __shared__ float sm[];
    float* Qs = sm;                    // [80][QP]
    float* Ks = Qs + 80 * QP;          // [80][QP]
    float* Vs = Ks + 80 * QP;          // [80][VP]
    float* Ps = Vs + 80 * VP;          // [64][PP]

    const int tid  = threadIdx.x;
    const int tx   = tid & 15;
    const int ty   = tid >> 4;
    const int trow = tid >> 2;   // 0..63 (row within tile for loads)
    const int tq   = tid & 3;    // 4 threads per row

    // ---- load Q tile (transposed into smem) ----
    {
        const float* qbase = g_q + (size_t)(b * cN + qt * 64 + trow) * cInner + h * cD;
#pragma unroll
        for (int i = 0; i < 5; i++) {
            const int d4 = (i * 4 + tq) * 4;
            float4 v = *(const float4*)(qbase + d4);
            Qs[(d4 + 0) * QP + trow] = v.x;
            Qs[(d4 + 1) * QP + trow] = v.y;
            Qs[(d4 + 2) * QP + trow] = v.z;
            Qs[(d4 + 3) * QP + trow] = v.w;
        }
    }

    float acc[4][5];
#pragma unroll
    for (int i = 0; i < 4; i++)
#pragma unroll
        for (int c = 0; c < 5; c++) acc[i][c] = 0.f;
    float m_i[4] = {-1e30f, -1e30f, -1e30f, -1e30f};
    float l_i[4] = {0.f, 0.f, 0.f, 0.f};

    const int frame0 = ctx[b * cR + 0];
    const int frame1 = ctx[b * cR + 1];
    const int frame2 = ctx[b * cR + 2];

    for (int t = 0; t < cRN / 64; t++) {
        __syncthreads();   // protect Ks/Vs/Ps from previous iteration's readers

        // ---- load K/V tile (transposed) ----
        {
            const int fidx  = t >> 4;
            const int frame = (fidx == 0) ? frame0 : (fidx == 1) ? frame1 : frame2;
            const int rowb  = (t * 64) & (cN - 1);
            const size_t off = (size_t)(frame * cN + rowb + trow) * cInner + h * cD;
            const float* kbase = g_k + off;
            const float* vbase = g_v + off;
#pragma unroll
            for (int i = 0; i < 5; i++) {
                const int d4 = (i * 4 + tq) * 4;
                float4 kv = *(const float4*)(kbase + d4);
                float4 vv = *(const float4*)(vbase + d4);
                Ks[(d4 + 0) * QP + trow] = kv.x;
                Ks[(d4 + 1) * QP + trow] = kv.y;
                Ks[(d4 + 2) * QP + trow] = kv.z;
                Ks[(d4 + 3) * QP + trow] = kv.w;
                Vs[(d4 + 0) * VP + trow] = vv.x;
                Vs[(d4 + 1) * VP + trow] = vv.y;
                Vs[(d4 + 2) * VP + trow] = vv.z;
                Vs[(d4 + 3) * VP + trow] = vv.w;
            }
        }
        __syncthreads();

        // ---- S = Q K^T (4x4 per thread) ----
        float s[4][4];
#pragma unroll
        for (int i = 0; i < 4; i++)
#pragma unroll
            for (int j = 0; j < 4; j++) s[i][j] = 0.f;

#pragma unroll 4
        for (int dk = 0; dk < cD; dk++) {
            float4 qv = *(const float4*)(Qs + dk * QP + ty * 4);
            float4 kv = *(const float4*)(Ks + dk * QP + tx * 4);
            const float qa[4] = {qv.x, qv.y, qv.z, qv.w};
            const float ka[4] = {kv.x, kv.y, kv.z, kv.w};
#pragma unroll
            for (int i = 0; i < 4; i++)
#pragma unroll
                for (int j = 0; j < 4; j++)
                    s[i][j] = fmaf(qa[i], ka[j], s[i][j]);
        }

        // ---- online softmax update ----
#pragma unroll
        for (int i = 0; i < 4; i++) {
#pragma unroll
            for (int j = 0; j < 4; j++) s[i][j] *= SCALE;
            float rm = fmaxf(fmaxf(s[i][0], s[i][1]), fmaxf(s[i][2], s[i][3]));
#pragma unroll
            for (int o = 8; o >= 1; o >>= 1)
                rm = fmaxf(rm, __shfl_xor_sync(0xffffffffu, rm, o));
            const float newm = fmaxf(m_i[i], rm);
            const float cf = __expf(m_i[i] - newm);
            float p[4];
            float rs = 0.f;
#pragma unroll
            for (int j = 0; j < 4; j++) {
                p[j] = __expf(s[i][j] - newm);
                rs += p[j];
            }
#pragma unroll
            for (int o = 8; o >= 1; o >>= 1)
                rs += __shfl_xor_sync(0xffffffffu, rs, o);
            l_i[i] = l_i[i] * cf + rs;
            m_i[i] = newm;
#pragma unroll
            for (int c = 0; c < 5; c++) acc[i][c] *= cf;
            *(float4*)(Ps + (ty * 4 + i) * PP + tx * 4) =
                make_float4(p[0], p[1], p[2], p[3]);
        }
        __syncthreads();

        // ---- O += P V  (rows ty*4+i, cols c*16+tx) ----
#pragma unroll 2
        for (int j = 0; j < 64; j += 4) {
            float pr[4][4];
#pragma unroll
            for (int i = 0; i < 4; i++) {
                float4 pv = *(const float4*)(Ps + (ty * 4 + i) * PP + j);
                pr[i][0] = pv.x; pr[i][1] = pv.y; pr[i][2] = pv.z; pr[i][3] = pv.w;
            }
#pragma unroll
            for (int jj = 0; jj < 4; jj++) {
                float vv[5];
#pragma unroll
                for (int c = 0; c < 5; c++)
                    vv[c] = Vs[(c * 16 + tx) * VP + (j + jj)];
#pragma unroll
                for (int i = 0; i < 4; i++)
#pragma unroll
                    for (int c = 0; c < 5; c++)
                        acc[i][c] = fmaf(pr[i][jj], vv[c], acc[i][c]);
            }
        }
    }

    // ---- epilogue ----
    float invl[4];
#pragma unroll
    for (int i = 0; i < 4; i++) invl[i] = 1.f / l_i[i];
#pragma unroll
    for (int i = 0; i < 4; i++) {
        float* op = g_ao + (size_t)(b * cN + qt * 64 + ty * 4 + i) * cInner + h * cD;
#pragma unroll
        for (int c = 0; c < 5; c++)
            op[c * 16 + tx] = acc[i][c] * invl[i];
    }
}

// ---------------------------------------------------------------------------
extern "C" void kernel_launch(void* const* d_in, const int* in_sizes, int n_in,
                              void* d_out, int out_size)
{
    const float* x   = (const float*)d_in[0];
    const float* Wq  = (const float*)d_in[1];
    const float* Wk  = (const float*)d_in[2];
    const float* Wv  = (const float*)d_in[3];
    const float* Wo  = (const float*)d_in[4];
    const float* bo  = (const float*)d_in[5];
    const int*   ctx = (const int*)d_in[6];
    float* out = (float*)d_out;

    float* gq; cudaGetSymbolAddress((void**)&gq, g_q);
    float* gk; cudaGetSymbolAddress((void**)&gk, g_k);
    float* gv; cudaGetSymbolAddress((void**)&gv, g_v);
    float* gao; cudaGetSymbolAddress((void**)&gao, g_ao);

    static bool attr_set = false;
    if (!attr_set) {
        cudaFuncSetAttribute(attn_kernel,
                             cudaFuncAttributeMaxDynamicSharedMemorySize,
                             ATTN_SMEM);
        attr_set = true;
    }

    const dim3 gg(cInner / 128, cM / 128);   // (5, 64)
    sgemm_nt<<<gg, 256>>>(x, Wq, gq, nullptr, cM, cInner, cC);
    sgemm_nt<<<gg, 256>>>(x, Wk, gk, nullptr, cM, cInner, cC);
    sgemm_nt<<<gg, 256>>>(x, Wv, gv, nullptr, cM, cInner, cC);

    attn_kernel<<<dim3(cN / 64, cH, cB), 256, ATTN_SMEM>>>(ctx);

    sgemm_nt<<<dim3(cC / 128, cM / 128), 256>>>(gao, Wo, out, bo, cM, cC, cInner);
}

// round 3
// speedup vs baseline: 1.7360x; 1.7360x over previous
#include <cuda_runtime.h>
#include <cuda_bf16.h>
#include <cstdint>

// Problem constants
constexpr int cB = 8;
constexpr int cN = 1024;
constexpr int cC = 640;
constexpr int cH = 8;
constexpr int cD = 80;
constexpr int cR = 3;
constexpr int cInner = cH * cD;        // 640
constexpr int cM = cB * cN;            // 8192
constexpr float SCALE = 0.11180339887498949f;  // 80^-0.5

// Scratch
__device__ float g_q[cM * cInner];
__device__ float g_k[cM * cInner];
__device__ float g_v[cM * cInner];
__device__ float g_ao[cM * cInner];

// ---------------------------------------------------------------------------
// SGEMM (proven round-1 kernel): C[M,Nc] = A[M,K] * B[Nc,K]^T (+bias)
// ---------------------------------------------------------------------------
__global__ __launch_bounds__(256) void sgemm_nt(
    const float* __restrict__ A, const float* __restrict__ Bm,
    float* __restrict__ C, const float* __restrict__ bias,
    int M, int Nc, int K)
{
    __shared__ float As[8][128];
    __shared__ float Bs[8][128];

    const int tid  = threadIdx.x;
    const int tx   = tid & 15;
    const int ty   = tid >> 4;
    const int lrow = tid >> 1;
    const int lcol = (tid & 1) * 4;

    const float* Ap = A  + (size_t)(blockIdx.y * 128 + lrow) * K + lcol;
    const float* Bp = Bm + (size_t)(blockIdx.x * 128 + lrow) * K + lcol;

    float acc[8][8];
#pragma unroll
    for (int i = 0; i < 8; i++)
#pragma unroll
        for (int j = 0; j < 8; j++) acc[i][j] = 0.f;

    for (int k0 = 0; k0 < K; k0 += 8) {
        float4 av = *(const float4*)(Ap + k0);
        float4 bv = *(const float4*)(Bp + k0);
        As[lcol + 0][lrow] = av.x; As[lcol + 1][lrow] = av.y;
        As[lcol + 2][lrow] = av.z; As[lcol + 3][lrow] = av.w;
        Bs[lcol + 0][lrow] = bv.x; Bs[lcol + 1][lrow] = bv.y;
        Bs[lcol + 2][lrow] = bv.z; Bs[lcol + 3][lrow] = bv.w;
        __syncthreads();
#pragma unroll
        for (int kk = 0; kk < 8; kk++) {
            float ra[8], rb[8];
            *(float4*)(ra)     = *(const float4*)&As[kk][ty * 8];
            *(float4*)(ra + 4) = *(const float4*)&As[kk][ty * 8 + 4];
            *(float4*)(rb)     = *(const float4*)&Bs[kk][tx * 8];
            *(float4*)(rb + 4) = *(const float4*)&Bs[kk][tx * 8 + 4];
#pragma unroll
            for (int i = 0; i < 8; i++)
#pragma unroll
                for (int j = 0; j < 8; j++)
                    acc[i][j] = fmaf(ra[i], rb[j], acc[i][j]);
        }
        __syncthreads();
    }

    const int c0 = blockIdx.x * 128 + tx * 8;
    float badd[8];
#pragma unroll
    for (int j = 0; j < 8; j++) badd[j] = bias ? bias[c0 + j] : 0.f;

#pragma unroll
    for (int i = 0; i < 8; i++) {
        const int row = blockIdx.y * 128 + ty * 8 + i;
        float* cp = C + (size_t)row * Nc + c0;
        *(float4*)cp = make_float4(acc[i][0] + badd[0], acc[i][1] + badd[1],
                                   acc[i][2] + badd[2], acc[i][3] + badd[3]);
        *(float4*)(cp + 4) = make_float4(acc[i][4] + badd[4], acc[i][5] + badd[5],
                                         acc[i][6] + badd[6], acc[i][7] + badd[7]);
    }
}

// ---------------------------------------------------------------------------
// mma.sync tf32 helpers (plain sm_103 — NO arch-specific 'a' features)
// ---------------------------------------------------------------------------
__device__ __forceinline__ uint32_t tf32r(float x) {
    uint32_t r;
    asm("cvt.rna.tf32.f32 %0, %1;" : "=r"(r) : "f"(x));
    return r;
}
__device__ __forceinline__ float tf32rf(float x) {
    return __uint_as_float(tf32r(x));
}
__device__ __forceinline__ void mma_tf32(float* c, const uint32_t* a,
                                         uint32_t b0, uint32_t b1) {
    asm volatile(
        "mma.sync.aligned.m16n8k8.row.col.f32.tf32.tf32.f32 "
        "{%0,%1,%2,%3}, {%4,%5,%6,%7}, {%8,%9}, {%0,%1,%2,%3};"
        : "+f"(c[0]), "+f"(c[1]), "+f"(c[2]), "+f"(c[3])
        : "r"(a[0]), "r"(a[1]), "r"(a[2]), "r"(a[3]), "r"(b0), "r"(b1));
}

// ---------------------------------------------------------------------------
// Flash attention with mma.sync tf32.
// Grid (8 qtiles, 8 heads, 8 frames), 256 threads = 8 warps.
// Warp w owns query rows [w*16, w*16+16) of the CTA's 128-query tile.
// Per KV tile (128 keys): S = Q K^T (16 n-tiles x 10 k-steps of m16n8k8),
// register softmax (rows live in-warp), P C-frag -> A-frag via shfl,
// O += P V (16 k-tiles x 10 n-tiles) accumulated in C fragments.
//
// Smem: Qs[128][84] staging, Kt[80][136] (d-major), Vs[128][88].
// Pitches 136 and 88 are ==8 (mod 32) so the (tig,gid) B-fragment access
// pattern maps to 32 distinct banks.
// ---------------------------------------------------------------------------
constexpr int QSP = 84;
constexpr int KTP = 136;
constexpr int VSP = 88;
constexpr int SM_QS = 0;                       // floats
constexpr int SM_KT = 128 * QSP;               // 10752
constexpr int SM_VS = SM_KT + 80 * KTP;        // 21632
constexpr int ATTN_SMEM = (SM_VS + 128 * VSP) * 4;   // 131584 bytes

__global__ __launch_bounds__(256, 1) void attn_mma(const int* __restrict__ ctx)
{
    extern __shared__ float sm[];
    float* Qs = sm + SM_QS;
    float* Kt = sm + SM_KT;
    float* Vs = sm + SM_VS;

    const int tid  = threadIdx.x;
    const int wid  = tid >> 5;
    const int lane = tid & 31;
    const int gid  = lane >> 2;    // group (row) id 0..7
    const int tig  = lane & 3;     // thread in group
    const int m0   = wid * 16;     // warp's first query row in tile

    const int qt = blockIdx.x, h = blockIdx.y, b = blockIdx.z;

    const int r0 = tid >> 1;           // 0..127 (row for staging)
    const int d0 = (tid & 1) * 40;     // 0 or 40

    // ---- stage Q (SCALE folded, tf32-rounded) ----
    {
        const float* qp = g_q + (size_t)(b * cN + qt * 128 + r0) * cInner + h * cD + d0;
        float* qs = Qs + r0 * QSP + d0;
#pragma unroll
        for (int i = 0; i < 10; i++) {
            float4 v = *(const float4*)(qp + i * 4);
            qs[i * 4 + 0] = tf32rf(v.x * SCALE);
            qs[i * 4 + 1] = tf32rf(v.y * SCALE);
            qs[i * 4 + 2] = tf32rf(v.z * SCALE);
            qs[i * 4 + 3] = tf32rf(v.w * SCALE);
        }
    }
    __syncthreads();

    // ---- load Q A-fragments into registers (reused for all 24 KV tiles) ----
    uint32_t qa[10][4];
#pragma unroll
    for (int k = 0; k < 10; k++) {
        qa[k][0] = __float_as_uint(Qs[(m0 + gid) * QSP + k * 8 + tig]);
        qa[k][1] = __float_as_uint(Qs[(m0 + gid + 8) * QSP + k * 8 + tig]);
        qa[k][2] = __float_as_uint(Qs[(m0 + gid) * QSP + k * 8 + tig + 4]);
        qa[k][3] = __float_as_uint(Qs[(m0 + gid + 8) * QSP + k * 8 + tig + 4]);
    }

    float o[10][4];
#pragma unroll
    for (int n = 0; n < 10; n++)
#pragma unroll
        for (int j = 0; j < 4; j++) o[n][j] = 0.f;
    float mlo = -1e30f, mhi = -1e30f, llo = 0.f, lhi = 0.f;

    const int sh1 = (lane & 28) | (tig >> 1);   // shfl src for col tig
    const int sh2 = sh1 + 2;                    // shfl src for col tig+4
    const bool odd = (tig & 1);

#pragma unroll 1
    for (int t = 0; t < 24; t++) {
        __syncthreads();   // prev tile's Kt/Vs readers done

        // ---- stage K (transposed, d-major) and V ----
        {
            const int frame = ctx[b * cR + (t >> 3)];
            const int kb = (t * 128) & (cN - 1);
            const size_t gof = (size_t)(frame * cN + kb + r0) * cInner + h * cD + d0;
            const float* kp = g_k + gof;
            const float* vp = g_v + gof;
            float* vs = Vs + r0 * VSP + d0;
#pragma unroll
            for (int i = 0; i < 10; i++) {
                float4 kv = *(const float4*)(kp + i * 4);
                Kt[(d0 + i * 4 + 0) * KTP + r0] = tf32rf(kv.x);
                Kt[(d0 + i * 4 + 1) * KTP + r0] = tf32rf(kv.y);
                Kt[(d0 + i * 4 + 2) * KTP + r0] = tf32rf(kv.z);
                Kt[(d0 + i * 4 + 3) * KTP + r0] = tf32rf(kv.w);
                float4 vv = *(const float4*)(vp + i * 4);
                *(float4*)(vs + i * 4) = make_float4(
                    tf32rf(vv.x), tf32rf(vv.y), tf32rf(vv.z), tf32rf(vv.w));
            }
        }
        __syncthreads();

        // ---- S = Q K^T : 16 n-tiles x 10 k-steps ----
        float s[16][4];
#pragma unroll
        for (int n = 0; n < 16; n++)
#pragma unroll
            for (int j = 0; j < 4; j++) s[n][j] = 0.f;

#pragma unroll
        for (int n = 0; n < 16; n++) {
            const float* kcol = Kt + n * 8 + gid;
#pragma unroll
            for (int k = 0; k < 10; k++) {
                uint32_t b0 = __float_as_uint(kcol[(k * 8 + tig) * KTP]);
                uint32_t b1 = __float_as_uint(kcol[(k * 8 + tig + 4) * KTP]);
                mma_tf32(s[n], qa[k], b0, b1);
            }
        }

        // ---- online softmax (register fragments; rows in-warp) ----
        float mx0 = -1e30f, mx1 = -1e30f;
#pragma unroll
        for (int n = 0; n < 16; n++) {
            mx0 = fmaxf(mx0, fmaxf(s[n][0], s[n][1]));
            mx1 = fmaxf(mx1, fmaxf(s[n][2], s[n][3]));
        }
        mx0 = fmaxf(mx0, __shfl_xor_sync(0xffffffffu, mx0, 1));
        mx0 = fmaxf(mx0, __shfl_xor_sync(0xffffffffu, mx0, 2));
        mx1 = fmaxf(mx1, __shfl_xor_sync(0xffffffffu, mx1, 1));
        mx1 = fmaxf(mx1, __shfl_xor_sync(0xffffffffu, mx1, 2));

        const float mn0 = fmaxf(mlo, mx0);
        const float mn1 = fmaxf(mhi, mx1);
        const float cf0 = __expf(mlo - mn0);
        const float cf1 = __expf(mhi - mn1);
        mlo = mn0; mhi = mn1;

        float rs0 = 0.f, rs1 = 0.f;
#pragma unroll
        for (int n = 0; n < 16; n++) {
            s[n][0] = __expf(s[n][0] - mn0); rs0 += s[n][0];
            s[n][1] = __expf(s[n][1] - mn0); rs0 += s[n][1];
            s[n][2] = __expf(s[n][2] - mn1); rs1 += s[n][2];
            s[n][3] = __expf(s[n][3] - mn1); rs1 += s[n][3];
        }
        rs0 += __shfl_xor_sync(0xffffffffu, rs0, 1);
        rs0 += __shfl_xor_sync(0xffffffffu, rs0, 2);
        rs1 += __shfl_xor_sync(0xffffffffu, rs1, 1);
        rs1 += __shfl_xor_sync(0xffffffffu, rs1, 2);
        llo = llo * cf0 + rs0;
        lhi = lhi * cf1 + rs1;

#pragma unroll
        for (int n = 0; n < 10; n++) {
            o[n][0] *= cf0; o[n][1] *= cf0;
            o[n][2] *= cf1; o[n][3] *= cf1;
        }

        // ---- O += P V : 16 k-tiles x 10 n-tiles ----
#pragma unroll
        for (int kt = 0; kt < 16; kt++) {
            // C-frag -> A-frag within the 4-lane group
            float v00 = __shfl_sync(0xffffffffu, s[kt][0], sh1);
            float v01 = __shfl_sync(0xffffffffu, s[kt][1], sh1);
            float v02 = __shfl_sync(0xffffffffu, s[kt][0], sh2);
            float v03 = __shfl_sync(0xffffffffu, s[kt][1], sh2);
            float v10 = __shfl_sync(0xffffffffu, s[kt][2], sh1);
            float v11 = __shfl_sync(0xffffffffu, s[kt][3], sh1);
            float v12 = __shfl_sync(0xffffffffu, s[kt][2], sh2);
            float v13 = __shfl_sync(0xffffffffu, s[kt][3], sh2);
            uint32_t pa[4];
            pa[0] = tf32r(odd ? v01 : v00);   // (row gid,   col kt*8+tig)
            pa[1] = tf32r(odd ? v11 : v10);   // (row gid+8, col kt*8+tig)
            pa[2] = tf32r(odd ? v03 : v02);   // (row gid,   col kt*8+tig+4)
            pa[3] = tf32r(odd ? v13 : v12);   // (row gid+8, col kt*8+tig+4)

            const float* vrow0 = Vs + (kt * 8 + tig) * VSP + gid;
            const float* vrow1 = Vs + (kt * 8 + tig + 4) * VSP + gid;
#pragma unroll
            for (int n = 0; n < 10; n++) {
                uint32_t b0 = __float_as_uint(vrow0[n * 8]);
                uint32_t b1 = __float_as_uint(vrow1[n * 8]);
                mma_tf32(o[n], pa, b0, b1);
            }
        }
    }

    // ---- epilogue ----
    const float inv0 = 1.f / llo;
    const float inv1 = 1.f / lhi;
    float* op0 = g_ao + (size_t)(b * cN + qt * 128 + m0 + gid) * cInner + h * cD;
    float* op1 = op0 + (size_t)8 * cInner;
#pragma unroll
    for (int n = 0; n < 10; n++) {
        *(float2*)(op0 + n * 8 + tig * 2) = make_float2(o[n][0] * inv0, o[n][1] * inv0);
        *(float2*)(op1 + n * 8 + tig * 2) = make_float2(o[n][2] * inv1, o[n][3] * inv1);
    }
}

// ---------------------------------------------------------------------------
extern "C" void kernel_launch(void* const* d_in, const int* in_sizes, int n_in,
                              void* d_out, int out_size)
{
    const float* x   = (const float*)d_in[0];
    const float* Wq  = (const float*)d_in[1];
    const float* Wk  = (const float*)d_in[2];
    const float* Wv  = (const float*)d_in[3];
    const float* Wo  = (const float*)d_in[4];
    const float* bo  = (const float*)d_in[5];
    const int*   ctx = (const int*)d_in[6];
    float* out = (float*)d_out;

    float* gq;  cudaGetSymbolAddress((void**)&gq, g_q);
    float* gk;  cudaGetSymbolAddress((void**)&gk, g_k);
    float* gv;  cudaGetSymbolAddress((void**)&gv, g_v);
    float* gao; cudaGetSymbolAddress((void**)&gao, g_ao);

    static bool attr_set = false;
    if (!attr_set) {
        cudaFuncSetAttribute(attn_mma,
                             cudaFuncAttributeMaxDynamicSharedMemorySize,
                             ATTN_SMEM);
        attr_set = true;
    }

    const dim3 gg(cInner / 128, cM / 128);
    sgemm_nt<<<gg, 256>>>(x, Wq, gq, nullptr, cM, cInner, cC);
    sgemm_nt<<<gg, 256>>>(x, Wk, gk, nullptr, cM, cInner, cC);
    sgemm_nt<<<gg, 256>>>(x, Wv, gv, nullptr, cM, cInner, cC);

    attn_mma<<<dim3(8, 8, 8), 256, ATTN_SMEM>>>(ctx);

    sgemm_nt<<<dim3(cC / 128, cM / 128), 256>>>(gao, Wo, out, bo, cM, cC, cInner);
}

// round 4
// speedup vs baseline: 2.3588x; 1.3588x over previous
#include <cuda_runtime.h>
#include <cuda_bf16.h>
#include <cstdint>

// Problem constants
constexpr int cB = 8;
constexpr int cN = 1024;
constexpr int cC = 640;
constexpr int cH = 8;
constexpr int cD = 80;
constexpr int cR = 3;
constexpr int cInner = cH * cD;        // 640
constexpr int cM = cB * cN;            // 8192
constexpr float SCALE = 0.11180339887498949f;  // 80^-0.5

// Scratch
__device__ float g_q[cM * cInner];
__device__ float g_k[cM * cInner];
__device__ float g_v[cM * cInner];
__device__ float g_ao[cM * cInner];

// ---------------------------------------------------------------------------
// mma.sync tf32 helpers (plain sm_103 — NO arch-specific 'a' features)
// ---------------------------------------------------------------------------
__device__ __forceinline__ uint32_t tf32r(float x) {
    uint32_t r;
    asm("cvt.rna.tf32.f32 %0, %1;" : "=r"(r) : "f"(x));
    return r;
}
__device__ __forceinline__ float tf32rf(float x) {
    return __uint_as_float(tf32r(x));
}
__device__ __forceinline__ void mma_tf32(float* c, const uint32_t* a,
                                         uint32_t b0, uint32_t b1) {
    asm volatile(
        "mma.sync.aligned.m16n8k8.row.col.f32.tf32.tf32.f32 "
        "{%0,%1,%2,%3}, {%4,%5,%6,%7}, {%8,%9}, {%0,%1,%2,%3};"
        : "+f"(c[0]), "+f"(c[1]), "+f"(c[2]), "+f"(c[3])
        : "r"(a[0]), "r"(a[1]), "r"(a[2]), "r"(a[3]), "r"(b0), "r"(b1));
}

// ---------------------------------------------------------------------------
// tf32 tensor-core GEMM: C[M,Nc] = A[M,K] * B[Nc,K]^T (+bias)
// 128x128 tile, BK=32, 8 warps (2x4), 64x32 per warp.
// Smem layout: row pitch 40 words, k interleaved with perm8 so each fragment
// (k, k+4) pair is one LDS.64; pitch%32==8 => conflict-free fragment loads.
// ---------------------------------------------------------------------------
constexpr int GP = 40;   // smem row pitch in words

__global__ __launch_bounds__(256, 2) void gemm_tf32(
    const float* __restrict__ A, const float* __restrict__ Bm,
    float* __restrict__ C, const float* __restrict__ bias,
    int M, int Nc, int K)
{
    __shared__ float As[128 * GP];
    __shared__ float Bs[128 * GP];

    const int tid  = threadIdx.x;
    const int wid  = tid >> 5;
    const int lane = tid & 31;
    const int gid  = lane >> 2;
    const int tig  = lane & 3;
    const int wm   = (wid & 1) * 64;
    const int wn   = (wid >> 1) * 32;

    const int srow = tid >> 1;           // 0..127
    const int skh  = (tid & 1) * 16;     // k half 0/16

    const float* Ap = A  + (size_t)(blockIdx.y * 128 + srow) * K + skh;
    const float* Bp = Bm + (size_t)(blockIdx.x * 128 + srow) * K + skh;
    float* as = As + srow * GP;
    float* bs = Bs + srow * GP;

    float acc[4][4][4];
#pragma unroll
    for (int mi = 0; mi < 4; mi++)
#pragma unroll
        for (int nj = 0; nj < 4; nj++)
#pragma unroll
            for (int j = 0; j < 4; j++) acc[mi][nj][j] = 0.f;

    for (int k0 = 0; k0 < K; k0 += 32) {
        __syncthreads();
#pragma unroll
        for (int c = 0; c < 4; c++) {
            float4 av = *(const float4*)(Ap + k0 + c * 4);
            float4 bv = *(const float4*)(Bp + k0 + c * 4);
            const int kb   = skh + c * 4;
            const int base = (kb & ~7) + ((kb & 4) ? 1 : 0);  // perm8 start
            as[base + 0] = tf32rf(av.x); as[base + 2] = tf32rf(av.y);
            as[base + 4] = tf32rf(av.z); as[base + 6] = tf32rf(av.w);
            bs[base + 0] = tf32rf(bv.x); bs[base + 2] = tf32rf(bv.y);
            bs[base + 4] = tf32rf(bv.z); bs[base + 6] = tf32rf(bv.w);
        }
        __syncthreads();

#pragma unroll
        for (int ks = 0; ks < 4; ks++) {
            uint32_t af[4][4];
#pragma unroll
            for (int mi = 0; mi < 4; mi++) {
                const float* p0 = As + (wm + mi * 16 + gid) * GP + ks * 8 + tig * 2;
                float2 x0 = *(const float2*)p0;              // (row gid,   k tig / tig+4)
                float2 x1 = *(const float2*)(p0 + 8 * GP);   // (row gid+8, k tig / tig+4)
                af[mi][0] = __float_as_uint(x0.x);
                af[mi][2] = __float_as_uint(x0.y);
                af[mi][1] = __float_as_uint(x1.x);
                af[mi][3] = __float_as_uint(x1.y);
            }
#pragma unroll
            for (int nj = 0; nj < 4; nj++) {
                const float* p = Bs + (wn + nj * 8 + gid) * GP + ks * 8 + tig * 2;
                float2 bb = *(const float2*)p;
                const uint32_t b0 = __float_as_uint(bb.x);
                const uint32_t b1 = __float_as_uint(bb.y);
#pragma unroll
                for (int mi = 0; mi < 4; mi++)
                    mma_tf32(acc[mi][nj], af[mi], b0, b1);
            }
        }
    }

    // epilogue
#pragma unroll
    for (int nj = 0; nj < 4; nj++) {
        const int col = blockIdx.x * 128 + wn + nj * 8 + tig * 2;
        const float ba0 = bias ? bias[col]     : 0.f;
        const float ba1 = bias ? bias[col + 1] : 0.f;
#pragma unroll
        for (int mi = 0; mi < 4; mi++) {
            const int row = blockIdx.y * 128 + wm + mi * 16 + gid;
            float* cp = C + (size_t)row * Nc + col;
            *(float2*)cp = make_float2(acc[mi][nj][0] + ba0, acc[mi][nj][1] + ba1);
            *(float2*)(cp + (size_t)8 * Nc) =
                make_float2(acc[mi][nj][2] + ba0, acc[mi][nj][3] + ba1);
        }
    }
}

// ---------------------------------------------------------------------------
// Flash attention with mma.sync tf32 (unchanged from round 3, passing config).
// ---------------------------------------------------------------------------
constexpr int QSP = 84;
constexpr int KTP = 136;
constexpr int VSP = 88;
constexpr int SM_QS = 0;
constexpr int SM_KT = 128 * QSP;
constexpr int SM_VS = SM_KT + 80 * KTP;
constexpr int ATTN_SMEM = (SM_VS + 128 * VSP) * 4;   // 131584 bytes

__global__ __launch_bounds__(256, 1) void attn_mma(const int* __restrict__ ctx)
{
    extern __shared__ float sm[];
    float* Qs = sm + SM_QS;
    float* Kt = sm + SM_KT;
    float* Vs = sm + SM_VS;

    const int tid  = threadIdx.x;
    const int wid  = tid >> 5;
    const int lane = tid & 31;
    const int gid  = lane >> 2;
    const int tig  = lane & 3;
    const int m0   = wid * 16;

    const int qt = blockIdx.x, h = blockIdx.y, b = blockIdx.z;

    const int r0 = tid >> 1;
    const int d0 = (tid & 1) * 40;

    {
        const float* qp = g_q + (size_t)(b * cN + qt * 128 + r0) * cInner + h * cD + d0;
        float* qs = Qs + r0 * QSP + d0;
#pragma unroll
        for (int i = 0; i < 10; i++) {
            float4 v = *(const float4*)(qp + i * 4);
            qs[i * 4 + 0] = tf32rf(v.x * SCALE);
            qs[i * 4 + 1] = tf32rf(v.y * SCALE);
            qs[i * 4 + 2] = tf32rf(v.z * SCALE);
            qs[i * 4 + 3] = tf32rf(v.w * SCALE);
        }
    }
    __syncthreads();

    uint32_t qa[10][4];
#pragma unroll
    for (int k = 0; k < 10; k++) {
        qa[k][0] = __float_as_uint(Qs[(m0 + gid) * QSP + k * 8 + tig]);
        qa[k][1] = __float_as_uint(Qs[(m0 + gid + 8) * QSP + k * 8 + tig]);
        qa[k][2] = __float_as_uint(Qs[(m0 + gid) * QSP + k * 8 + tig + 4]);
        qa[k][3] = __float_as_uint(Qs[(m0 + gid + 8) * QSP + k * 8 + tig + 4]);
    }

    float o[10][4];
#pragma unroll
    for (int n = 0; n < 10; n++)
#pragma unroll
        for (int j = 0; j < 4; j++) o[n][j] = 0.f;
    float mlo = -1e30f, mhi = -1e30f, llo = 0.f, lhi = 0.f;

    const int sh1 = (lane & 28) | (tig >> 1);
    const int sh2 = sh1 + 2;
    const bool odd = (tig & 1);

#pragma unroll 1
    for (int t = 0; t < 24; t++) {
        __syncthreads();

        {
            const int frame = ctx[b * cR + (t >> 3)];
            const int kb = (t * 128) & (cN - 1);
            const size_t gof = (size_t)(frame * cN + kb + r0) * cInner + h * cD + d0;
            const float* kp = g_k + gof;
            const float* vp = g_v + gof;
            float* vs = Vs + r0 * VSP + d0;
#pragma unroll
            for (int i = 0; i < 10; i++) {
                float4 kv = *(const float4*)(kp + i * 4);
                Kt[(d0 + i * 4 + 0) * KTP + r0] = tf32rf(kv.x);
                Kt[(d0 + i * 4 + 1) * KTP + r0] = tf32rf(kv.y);
                Kt[(d0 + i * 4 + 2) * KTP + r0] = tf32rf(kv.z);
                Kt[(d0 + i * 4 + 3) * KTP + r0] = tf32rf(kv.w);
                float4 vv = *(const float4*)(vp + i * 4);
                *(float4*)(vs + i * 4) = make_float4(
                    tf32rf(vv.x), tf32rf(vv.y), tf32rf(vv.z), tf32rf(vv.w));
            }
        }
        __syncthreads();

        float s[16][4];
#pragma unroll
        for (int n = 0; n < 16; n++)
#pragma unroll
            for (int j = 0; j < 4; j++) s[n][j] = 0.f;

#pragma unroll
        for (int n = 0; n < 16; n++) {
            const float* kcol = Kt + n * 8 + gid;
#pragma unroll
            for (int k = 0; k < 10; k++) {
                uint32_t b0 = __float_as_uint(kcol[(k * 8 + tig) * KTP]);
                uint32_t b1 = __float_as_uint(kcol[(k * 8 + tig + 4) * KTP]);
                mma_tf32(s[n], qa[k], b0, b1);
            }
        }

        float mx0 = -1e30f, mx1 = -1e30f;
#pragma unroll
        for (int n = 0; n < 16; n++) {
            mx0 = fmaxf(mx0, fmaxf(s[n][0], s[n][1]));
            mx1 = fmaxf(mx1, fmaxf(s[n][2], s[n][3]));
        }
        mx0 = fmaxf(mx0, __shfl_xor_sync(0xffffffffu, mx0, 1));
        mx0 = fmaxf(mx0, __shfl_xor_sync(0xffffffffu, mx0, 2));
        mx1 = fmaxf(mx1, __shfl_xor_sync(0xffffffffu, mx1, 1));
        mx1 = fmaxf(mx1, __shfl_xor_sync(0xffffffffu, mx1, 2));

        const float mn0 = fmaxf(mlo, mx0);
        const float mn1 = fmaxf(mhi, mx1);
        const float cf0 = __expf(mlo - mn0);
        const float cf1 = __expf(mhi - mn1);
        mlo = mn0; mhi = mn1;

        float rs0 = 0.f, rs1 = 0.f;
#pragma unroll
        for (int n = 0; n < 16; n++) {
            s[n][0] = __expf(s[n][0] - mn0); rs0 += s[n][0];
            s[n][1] = __expf(s[n][1] - mn0); rs0 += s[n][1];
            s[n][2] = __expf(s[n][2] - mn1); rs1 += s[n][2];
            s[n][3] = __expf(s[n][3] - mn1); rs1 += s[n][3];
        }
        rs0 += __shfl_xor_sync(0xffffffffu, rs0, 1);
        rs0 += __shfl_xor_sync(0xffffffffu, rs0, 2);
        rs1 += __shfl_xor_sync(0xffffffffu, rs1, 1);
        rs1 += __shfl_xor_sync(0xffffffffu, rs1, 2);
        llo = llo * cf0 + rs0;
        lhi = lhi * cf1 + rs1;

#pragma unroll
        for (int n = 0; n < 10; n++) {
            o[n][0] *= cf0; o[n][1] *= cf0;
            o[n][2] *= cf1; o[n][3] *= cf1;
        }

#pragma unroll
        for (int kt = 0; kt < 16; kt++) {
            float v00 = __shfl_sync(0xffffffffu, s[kt][0], sh1);
            float v01 = __shfl_sync(0xffffffffu, s[kt][1], sh1);
            float v02 = __shfl_sync(0xffffffffu, s[kt][0], sh2);
            float v03 = __shfl_sync(0xffffffffu, s[kt][1], sh2);
            float v10 = __shfl_sync(0xffffffffu, s[kt][2], sh1);
            float v11 = __shfl_sync(0xffffffffu, s[kt][3], sh1);
            float v12 = __shfl_sync(0xffffffffu, s[kt][2], sh2);
            float v13 = __shfl_sync(0xffffffffu, s[kt][3], sh2);
            uint32_t pa[4];
            pa[0] = tf32r(odd ? v01 : v00);
            pa[1] = tf32r(odd ? v11 : v10);
            pa[2] = tf32r(odd ? v03 : v02);
            pa[3] = tf32r(odd ? v13 : v12);

            const float* vrow0 = Vs + (kt * 8 + tig) * VSP + gid;
            const float* vrow1 = Vs + (kt * 8 + tig + 4) * VSP + gid;
#pragma unroll
            for (int n = 0; n < 10; n++) {
                uint32_t b0 = __float_as_uint(vrow0[n * 8]);
                uint32_t b1 = __float_as_uint(vrow1[n * 8]);
                mma_tf32(o[n], pa, b0, b1);
            }
        }
    }

    const float inv0 = 1.f / llo;
    const float inv1 = 1.f / lhi;
    float* op0 = g_ao + (size_t)(b * cN + qt * 128 + m0 + gid) * cInner + h * cD;
    float* op1 = op0 + (size_t)8 * cInner;
#pragma unroll
    for (int n = 0; n < 10; n++) {
        *(float2*)(op0 + n * 8 + tig * 2) = make_float2(o[n][0] * inv0, o[n][1] * inv0);
        *(float2*)(op1 + n * 8 + tig * 2) = make_float2(o[n][2] * inv1, o[n][3] * inv1);
    }
}

// ---------------------------------------------------------------------------
extern "C" void kernel_launch(void* const* d_in, const int* in_sizes, int n_in,
                              void* d_out, int out_size)
{
    const float* x   = (const float*)d_in[0];
    const float* Wq  = (const float*)d_in[1];
    const float* Wk  = (const float*)d_in[2];
    const float* Wv  = (const float*)d_in[3];
    const float* Wo  = (const float*)d_in[4];
    const float* bo  = (const float*)d_in[5];
    const int*   ctx = (const int*)d_in[6];
    float* out = (float*)d_out;

    float* gq;  cudaGetSymbolAddress((void**)&gq, g_q);
    float* gk;  cudaGetSymbolAddress((void**)&gk, g_k);
    float* gv;  cudaGetSymbolAddress((void**)&gv, g_v);
    float* gao; cudaGetSymbolAddress((void**)&gao, g_ao);

    static bool attr_set = false;
    if (!attr_set) {
        cudaFuncSetAttribute(attn_mma,
                             cudaFuncAttributeMaxDynamicSharedMemorySize,
                             ATTN_SMEM);
        attr_set = true;
    }

    const dim3 gg(cInner / 128, cM / 128);   // (5, 64)
    gemm_tf32<<<gg, 256>>>(x, Wq, gq, nullptr, cM, cInner, cC);
    gemm_tf32<<<gg, 256>>>(x, Wk, gk, nullptr, cM, cInner, cC);
    gemm_tf32<<<gg, 256>>>(x, Wv, gv, nullptr, cM, cInner, cC);

    attn_mma<<<dim3(8, 8, 8), 256, ATTN_SMEM>>>(ctx);

    gemm_tf32<<<dim3(cC / 128, cM / 128), 256>>>(gao, Wo, out, bo, cM, cC, cInner);
}